// round 2
// baseline (speedup 1.0000x reference)
#include <cuda_runtime.h>
#include <math.h>

#define TSTEPS 1024
#define BSZ    128
#define DDIM   512
#define HDIM   1024
#define ODIM   128
#define NBLK   256

// Persistent device scratch (no allocations allowed)
__device__ float g_h1[2 * BSZ * HDIM];
__device__ float g_c1[BSZ * HDIM];
__device__ float g_h2[BSZ * HDIM];
__device__ float g_c2[BSZ * HDIM];
__device__ float g_z2p[BSZ * 4 * HDIM];
__device__ float g_hist[(size_t)TSTEPS * BSZ * HDIM];
__device__ unsigned g_bar[2];   // [0]=count, [1]=generation

typedef unsigned long long ull;

// Blackwell packed double-rate fp32 FMA — only reachable via PTX f32x2.
#define FMA2(d, a, b) asm("fma.rn.f32x2 %0, %1, %2, %0;" : "+l"(d) : "l"(a), "l"(b))

__device__ __forceinline__ ull dup2(float b) {
    ull r; asm("mov.b64 %0, {%1, %1};" : "=l"(r) : "f"(b)); return r;
}
__device__ __forceinline__ float2 unpk(ull v) {
    float2 r; asm("mov.b64 {%0, %1}, %2;" : "=f"(r.x), "=f"(r.y) : "l"(v)); return r;
}
__device__ __forceinline__ float sigm(float x) { return 1.0f / (1.0f + expf(-x)); }

// Software grid barrier (all NBLK blocks are co-resident by construction).
__device__ __forceinline__ void gsync() {
    __syncthreads();
    if (threadIdx.x == 0) {
        volatile unsigned* vgen = (volatile unsigned*)&g_bar[1];
        unsigned gen = *vgen;
        __threadfence();
        if (atomicAdd(&g_bar[0], 1u) == NBLK - 1) {
            g_bar[0] = 0;
            __threadfence();
            *vgen = gen + 1;
        } else {
            while (*vgen == gen) { }
        }
    }
    __syncthreads();
}

// ---------------------------------------------------------------------------
// Tile GEMM: acc += A[RT x K] @ B^T, output tile [RT x 32], RT = 32*RPAIRS.
// 128 threads: colg = tid&7 -> 4 cols each; rowg = tid>>3 -> 2*RPAIRS rows.
// SMEM XOR swizzle (idx ^ (kk&28)) makes transpose stores AND LDS.128 reads
// bank-conflict-free.
// gate_mode: tile col c maps to B row (c>>3)*HDIM + nb + (c&7)  (i,f,g,o).
// ---------------------------------------------------------------------------
template<int RPAIRS>
__device__ __forceinline__ void gemm_tile(
    ull (&acc)[RPAIRS][4],
    const float* __restrict__ A, int lda,
    const float* __restrict__ Bw, int ldb, int K,
    int gate_mode, int nb,
    float* As, float* Bs, int tid)
{
    const int RT = RPAIRS * 32;
    int rowg = tid >> 3, colg = tid & 7;
    int r0 = rowg * 2 * RPAIRS;
    int c0 = colg * 4;

    for (int k0 = 0; k0 < K; k0 += 32) {
        // Load A tile [RT x 32] -> As[kk][row ^ (kk&28)]
        #pragma unroll
        for (int i = 0; i < RT / 16; i++) {
            int f4 = tid + i * 128;
            int row = f4 >> 3;
            int kc  = (f4 & 7) << 2;
            float4 v = *(const float4*)(A + (size_t)row * lda + k0 + kc);
            int sw = kc & 28;                 // (kc+u)&28 == kc&28 for u<4
            As[(kc + 0) * 128 + (row ^ sw)] = v.x;
            As[(kc + 1) * 128 + (row ^ sw)] = v.y;
            As[(kc + 2) * 128 + (row ^ sw)] = v.z;
            As[(kc + 3) * 128 + (row ^ sw)] = v.w;
        }
        // Load B tile [32 x 32] -> Bs[kk][col ^ (kk&28)]
        #pragma unroll
        for (int i = 0; i < 2; i++) {
            int f4 = tid + i * 128;
            int col = f4 >> 3;
            int kc  = (f4 & 7) << 2;
            int brow = gate_mode ? ((col >> 3) * HDIM + nb + (col & 7))
                                 : (nb + col);
            float4 v = *(const float4*)(Bw + (size_t)brow * ldb + k0 + kc);
            int sw = kc & 28;
            Bs[(kc + 0) * 32 + (col ^ sw)] = v.x;
            Bs[(kc + 1) * 32 + (col ^ sw)] = v.y;
            Bs[(kc + 2) * 32 + (col ^ sw)] = v.z;
            Bs[(kc + 3) * 32 + (col ^ sw)] = v.w;
        }
        __syncthreads();
        #pragma unroll
        for (int kk = 0; kk < 32; kk++) {
            int sw = kk & 28;
            float4 bv = *(const float4*)&Bs[kk * 32 + (c0 ^ sw)];
            ull b0 = dup2(bv.x), b1 = dup2(bv.y), b2 = dup2(bv.z), b3 = dup2(bv.w);
            #pragma unroll
            for (int rpb = 0; rpb < RPAIRS / 2; rpb++) {
                int rb = r0 + rpb * 4;
                ulonglong2 av = *(const ulonglong2*)&As[kk * 128 + (rb ^ sw)];
                FMA2(acc[rpb*2 + 0][0], av.x, b0);
                FMA2(acc[rpb*2 + 0][1], av.x, b1);
                FMA2(acc[rpb*2 + 0][2], av.x, b2);
                FMA2(acc[rpb*2 + 0][3], av.x, b3);
                FMA2(acc[rpb*2 + 1][0], av.y, b0);
                FMA2(acc[rpb*2 + 1][1], av.y, b1);
                FMA2(acc[rpb*2 + 1][2], av.y, b2);
                FMA2(acc[rpb*2 + 1][3], av.y, b3);
            }
        }
        __syncthreads();
    }
}

// Stage accumulators into zs[row*33 + col] (stride 33 pad).
template<int RPAIRS>
__device__ __forceinline__ void stage_z(float* zs, ull (&acc)[RPAIRS][4], int tid) {
    int rowg = tid >> 3, colg = tid & 7;
    int r0 = rowg * 2 * RPAIRS, c0 = colg * 4;
    #pragma unroll
    for (int rp = 0; rp < RPAIRS; rp++)
        #pragma unroll
        for (int c = 0; c < 4; c++) {
            float2 v = unpk(acc[rp][c]);
            zs[(r0 + 2*rp + 0) * 33 + c0 + c] = v.x;
            zs[(r0 + 2*rp + 1) * 33 + c0 + c] = v.y;
        }
}

__global__ void __launch_bounds__(128, 2)
lstm_persistent(const float* __restrict__ x,
                const float* __restrict__ W_ih1, const float* __restrict__ W_hh1,
                const float* __restrict__ b_ih1, const float* __restrict__ b_hh1,
                const float* __restrict__ W_ih2, const float* __restrict__ W_hh2,
                const float* __restrict__ b_ih2, const float* __restrict__ b_hh2)
{
    __shared__ float smem[5120];     // As 4096 | Bs 1024 ; zs (4224) overlays
    float* As = smem;
    float* Bs = smem + 4096;
    float* zs = smem;

    int tid = threadIdx.x;
    int jb  = blockIdx.x;

    for (int t = 0; t < TSTEPS; t++) {
        const float* h1r = g_h1 + (size_t)(t & 1) * BSZ * HDIM;
        float*       h1w = g_h1 + (size_t)((t + 1) & 1) * BSZ * HDIM;

        // ---------------- Phase A ----------------
        if (jb < 128) {
            // Layer-1 tile: cols [nb, nb+8) of each gate
            int nb = jb * 8;
            ull acc[4][4] = {};
            gemm_tile<4>(acc, h1r, HDIM, W_hh1, HDIM, HDIM, 1, nb, As, Bs, tid);
            gemm_tile<4>(acc, x + (size_t)t * BSZ * DDIM, DDIM, W_ih1, DDIM, DDIM,
                         1, nb, As, Bs, tid);
            stage_z<4>(zs, acc, tid);
            __syncthreads();
            for (int e = tid; e < 1024; e += 128) {
                int row = e >> 3, jj = e & 7;
                int col = nb + jj;
                float zi = zs[row*33 +      jj] + b_ih1[col]          + b_hh1[col];
                float zf = zs[row*33 +  8 + jj] + b_ih1[HDIM + col]   + b_hh1[HDIM + col];
                float zg = zs[row*33 + 16 + jj] + b_ih1[2*HDIM + col] + b_hh1[2*HDIM + col];
                float zo = zs[row*33 + 24 + jj] + b_ih1[3*HDIM + col] + b_hh1[3*HDIM + col];
                int sidx = row * HDIM + col;
                float cp = g_c1[sidx];
                float cn = sigm(zf) * cp + sigm(zi) * tanhf(zg);
                g_c1[sidx] = cn;
                h1w[sidx] = sigm(zo) * tanhf(cn);
            }
        } else {
            // z2p tile: z2p = h2_{t-1} @ W_hh2^T + b_ih2 + b_hh2
            int nb = (jb - 128) * 8;
            ull acc[4][4] = {};
            gemm_tile<4>(acc, g_h2, HDIM, W_hh2, HDIM, HDIM, 1, nb, As, Bs, tid);
            stage_z<4>(zs, acc, tid);
            __syncthreads();
            for (int e = tid; e < 4096; e += 128) {
                int row = e >> 5, c = e & 31;
                int col = (c >> 3) * HDIM + nb + (c & 7);
                g_z2p[(size_t)row * 4 * HDIM + col] =
                    zs[row*33 + c] + b_ih2[col] + b_hh2[col];
            }
        }
        gsync();

        // ---------------- Phase B: layer-2, 256 tiles [64 x 32] ----------------
        {
            int rt = jb >> 7;
            int nb = (jb & 127) * 8;
            int m0 = rt * 64;
            ull acc[2][4] = {};
            gemm_tile<2>(acc, h1w + (size_t)m0 * HDIM, HDIM, W_ih2, HDIM, HDIM,
                         1, nb, As, Bs, tid);
            stage_z<2>(zs, acc, tid);
            __syncthreads();
            for (int e = tid; e < 512; e += 128) {
                int row = e >> 3, jj = e & 7;
                int col = nb + jj;
                int grow = m0 + row;
                size_t zb = (size_t)grow * 4 * HDIM + col;
                float zi = zs[row*33 +      jj] + g_z2p[zb];
                float zf = zs[row*33 +  8 + jj] + g_z2p[zb + HDIM];
                float zg = zs[row*33 + 16 + jj] + g_z2p[zb + 2*HDIM];
                float zo = zs[row*33 + 24 + jj] + g_z2p[zb + 3*HDIM];
                int sidx = grow * HDIM + col;
                float cp = g_c2[sidx];
                float cn = sigm(zf) * cp + sigm(zi) * tanhf(zg);
                g_c2[sidx] = cn;
                float h = sigm(zo) * tanhf(cn);
                g_h2[sidx] = h;
                g_hist[(size_t)t * BSZ * HDIM + sidx] = h;
            }
        }
        gsync();
    }
}

// y = hist @ W_out^T + b_out, [T*B, O]; tiles [128 x 32], grid (4, 1024).
__global__ void __launch_bounds__(128, 2)
outproj(const float* __restrict__ W_out, const float* __restrict__ b_out,
        float* __restrict__ y)
{
    __shared__ float smem[5120];
    float* As = smem;
    float* Bs = smem + 4096;
    float* zs = smem;
    int tid = threadIdx.x;
    int m0 = blockIdx.y * 128;
    int nb = blockIdx.x * 32;
    ull acc[4][4] = {};
    gemm_tile<4>(acc, g_hist + (size_t)m0 * HDIM, HDIM, W_out, HDIM, HDIM,
                 0, nb, As, Bs, tid);
    stage_z<4>(zs, acc, tid);
    __syncthreads();
    for (int e = tid; e < 4096; e += 128) {
        int row = e >> 5, c = e & 31;
        y[(size_t)(m0 + row) * ODIM + nb + c] = zs[row*33 + c] + b_out[nb + c];
    }
}

extern "C" void kernel_launch(void* const* d_in, const int* in_sizes, int n_in,
                              void* d_out, int out_size) {
    const float* x     = (const float*)d_in[0];
    const float* W_ih1 = (const float*)d_in[1];
    const float* W_hh1 = (const float*)d_in[2];
    const float* b_ih1 = (const float*)d_in[3];
    const float* b_hh1 = (const float*)d_in[4];
    const float* W_ih2 = (const float*)d_in[5];
    const float* W_hh2 = (const float*)d_in[6];
    const float* b_ih2 = (const float*)d_in[7];
    const float* b_hh2 = (const float*)d_in[8];
    const float* W_out = (const float*)d_in[9];
    const float* b_out = (const float*)d_in[10];

    void *p_h1, *p_c1, *p_h2, *p_c2, *p_bar;
    cudaGetSymbolAddress(&p_h1, g_h1);
    cudaGetSymbolAddress(&p_c1, g_c1);
    cudaGetSymbolAddress(&p_h2, g_h2);
    cudaGetSymbolAddress(&p_c2, g_c2);
    cudaGetSymbolAddress(&p_bar, g_bar);

    size_t sb = (size_t)BSZ * HDIM * sizeof(float);
    cudaMemsetAsync(p_h1, 0, 2 * sb, 0);
    cudaMemsetAsync(p_c1, 0, sb, 0);
    cudaMemsetAsync(p_h2, 0, sb, 0);
    cudaMemsetAsync(p_c2, 0, sb, 0);
    cudaMemsetAsync(p_bar, 0, 2 * sizeof(unsigned), 0);

    lstm_persistent<<<NBLK, 128>>>(x, W_ih1, W_hh1, b_ih1, b_hh1,
                                   W_ih2, W_hh2, b_ih2, b_hh2);
    outproj<<<dim3(4, 1024), 128>>>(W_out, b_out, (float*)d_out);
}

// round 3
// speedup vs baseline: 1.0037x; 1.0037x over previous
#include <cuda_runtime.h>
#include <math.h>

#define TSTEPS 1024
#define BSZ    128
#define DDIM   512
#define HDIM   1024
#define ODIM   128
#define NBLK   256

// Persistent device scratch (no allocations allowed)
__device__ float g_h1[2 * BSZ * HDIM];
__device__ float g_c1[BSZ * HDIM];
__device__ float g_h2[BSZ * HDIM];
__device__ float g_c2[BSZ * HDIM];
__device__ float g_z2p[BSZ * 4 * HDIM];
__device__ float g_hist[(size_t)TSTEPS * BSZ * HDIM];
__device__ unsigned g_bar[2];   // [0]=count, [1]=generation

typedef unsigned long long ull;

// Blackwell packed double-rate fp32 FMA — only reachable via PTX f32x2.
#define FMA2(d, a, b) asm("fma.rn.f32x2 %0, %1, %2, %0;" : "+l"(d) : "l"(a), "l"(b))

__device__ __forceinline__ ull dup2(float b) {
    ull r; asm("mov.b64 %0, {%1, %1};" : "=l"(r) : "f"(b)); return r;
}
__device__ __forceinline__ float2 unpk(ull v) {
    float2 r; asm("mov.b64 {%0, %1}, %2;" : "=f"(r.x), "=f"(r.y) : "l"(v)); return r;
}
__device__ __forceinline__ float sigm(float x) { return 1.0f / (1.0f + expf(-x)); }

// Software grid barrier (all NBLK blocks are co-resident by construction).
__device__ __forceinline__ void gsync() {
    __syncthreads();
    if (threadIdx.x == 0) {
        volatile unsigned* vgen = (volatile unsigned*)&g_bar[1];
        unsigned gen = *vgen;
        __threadfence();
        if (atomicAdd(&g_bar[0], 1u) == NBLK - 1) {
            g_bar[0] = 0;
            __threadfence();
            *vgen = gen + 1;
        } else {
            while (*vgen == gen) { }
        }
    }
    __syncthreads();
}

// ---------------------------------------------------------------------------
// Tile GEMM: acc += A[RT x K] @ B^T, output tile [RT x 32], RT = 32*RPAIRS.
// 128 threads: colg = tid&7 -> 4 cols each; rowg = tid>>3 -> 2*RPAIRS rows.
// SMEM XOR swizzle (idx ^ (kk&28)) makes transpose stores AND LDS.128 reads
// bank-conflict-free.
// gate_mode: tile col c maps to B row (c>>3)*HDIM + nb + (c&7)  (i,f,g,o).
// ---------------------------------------------------------------------------
template<int RPAIRS>
__device__ __forceinline__ void gemm_tile(
    ull (&acc)[RPAIRS][4],
    const float* __restrict__ A, int lda,
    const float* __restrict__ Bw, int ldb, int K,
    int gate_mode, int nb,
    float* As, float* Bs, int tid)
{
    const int RT = RPAIRS * 32;
    int rowg = tid >> 3, colg = tid & 7;
    int r0 = rowg * 2 * RPAIRS;
    int c0 = colg * 4;

    for (int k0 = 0; k0 < K; k0 += 32) {
        // Load A tile [RT x 32] -> As[kk][row ^ (kk&28)]
        #pragma unroll
        for (int i = 0; i < RT / 16; i++) {
            int f4 = tid + i * 128;
            int row = f4 >> 3;
            int kc  = (f4 & 7) << 2;
            float4 v = *(const float4*)(A + (size_t)row * lda + k0 + kc);
            int sw = kc & 28;                 // (kc+u)&28 == kc&28 for u<4
            As[(kc + 0) * 128 + (row ^ sw)] = v.x;
            As[(kc + 1) * 128 + (row ^ sw)] = v.y;
            As[(kc + 2) * 128 + (row ^ sw)] = v.z;
            As[(kc + 3) * 128 + (row ^ sw)] = v.w;
        }
        // Load B tile [32 x 32] -> Bs[kk][col ^ (kk&28)]
        #pragma unroll
        for (int i = 0; i < 2; i++) {
            int f4 = tid + i * 128;
            int col = f4 >> 3;
            int kc  = (f4 & 7) << 2;
            int brow = gate_mode ? ((col >> 3) * HDIM + nb + (col & 7))
                                 : (nb + col);
            float4 v = *(const float4*)(Bw + (size_t)brow * ldb + k0 + kc);
            int sw = kc & 28;
            Bs[(kc + 0) * 32 + (col ^ sw)] = v.x;
            Bs[(kc + 1) * 32 + (col ^ sw)] = v.y;
            Bs[(kc + 2) * 32 + (col ^ sw)] = v.z;
            Bs[(kc + 3) * 32 + (col ^ sw)] = v.w;
        }
        __syncthreads();
        #pragma unroll
        for (int kk = 0; kk < 32; kk++) {
            int sw = kk & 28;
            float4 bv = *(const float4*)&Bs[kk * 32 + (c0 ^ sw)];
            ull b0 = dup2(bv.x), b1 = dup2(bv.y), b2 = dup2(bv.z), b3 = dup2(bv.w);
            #pragma unroll
            for (int rpb = 0; rpb < RPAIRS / 2; rpb++) {
                int rb = r0 + rpb * 4;
                ulonglong2 av = *(const ulonglong2*)&As[kk * 128 + (rb ^ sw)];
                FMA2(acc[rpb*2 + 0][0], av.x, b0);
                FMA2(acc[rpb*2 + 0][1], av.x, b1);
                FMA2(acc[rpb*2 + 0][2], av.x, b2);
                FMA2(acc[rpb*2 + 0][3], av.x, b3);
                FMA2(acc[rpb*2 + 1][0], av.y, b0);
                FMA2(acc[rpb*2 + 1][1], av.y, b1);
                FMA2(acc[rpb*2 + 1][2], av.y, b2);
                FMA2(acc[rpb*2 + 1][3], av.y, b3);
            }
        }
        __syncthreads();
    }
}

// Stage accumulators into zs[row*33 + col] (stride 33 pad).
template<int RPAIRS>
__device__ __forceinline__ void stage_z(float* zs, ull (&acc)[RPAIRS][4], int tid) {
    int rowg = tid >> 3, colg = tid & 7;
    int r0 = rowg * 2 * RPAIRS, c0 = colg * 4;
    #pragma unroll
    for (int rp = 0; rp < RPAIRS; rp++)
        #pragma unroll
        for (int c = 0; c < 4; c++) {
            float2 v = unpk(acc[rp][c]);
            zs[(r0 + 2*rp + 0) * 33 + c0 + c] = v.x;
            zs[(r0 + 2*rp + 1) * 33 + c0 + c] = v.y;
        }
}

__global__ void __launch_bounds__(128, 2)
lstm_persistent(const float* __restrict__ x,
                const float* __restrict__ W_ih1, const float* __restrict__ W_hh1,
                const float* __restrict__ b_ih1, const float* __restrict__ b_hh1,
                const float* __restrict__ W_ih2, const float* __restrict__ W_hh2,
                const float* __restrict__ b_ih2, const float* __restrict__ b_hh2)
{
    __shared__ float smem[5120];     // As 4096 | Bs 1024 ; zs (4224) overlays
    float* As = smem;
    float* Bs = smem + 4096;
    float* zs = smem;

    int tid = threadIdx.x;
    int jb  = blockIdx.x;

    for (int t = 0; t < TSTEPS; t++) {
        const float* h1r = g_h1 + (size_t)(t & 1) * BSZ * HDIM;
        float*       h1w = g_h1 + (size_t)((t + 1) & 1) * BSZ * HDIM;

        // ---------------- Phase A ----------------
        if (jb < 128) {
            // Layer-1 tile: cols [nb, nb+8) of each gate
            int nb = jb * 8;
            ull acc[4][4] = {};
            gemm_tile<4>(acc, h1r, HDIM, W_hh1, HDIM, HDIM, 1, nb, As, Bs, tid);
            gemm_tile<4>(acc, x + (size_t)t * BSZ * DDIM, DDIM, W_ih1, DDIM, DDIM,
                         1, nb, As, Bs, tid);
            stage_z<4>(zs, acc, tid);
            __syncthreads();
            for (int e = tid; e < 1024; e += 128) {
                int row = e >> 3, jj = e & 7;
                int col = nb + jj;
                float zi = zs[row*33 +      jj] + b_ih1[col]          + b_hh1[col];
                float zf = zs[row*33 +  8 + jj] + b_ih1[HDIM + col]   + b_hh1[HDIM + col];
                float zg = zs[row*33 + 16 + jj] + b_ih1[2*HDIM + col] + b_hh1[2*HDIM + col];
                float zo = zs[row*33 + 24 + jj] + b_ih1[3*HDIM + col] + b_hh1[3*HDIM + col];
                int sidx = row * HDIM + col;
                float cp = g_c1[sidx];
                float cn = sigm(zf) * cp + sigm(zi) * tanhf(zg);
                g_c1[sidx] = cn;
                h1w[sidx] = sigm(zo) * tanhf(cn);
            }
        } else {
            // z2p tile: z2p = h2_{t-1} @ W_hh2^T + b_ih2 + b_hh2
            int nb = (jb - 128) * 8;
            ull acc[4][4] = {};
            gemm_tile<4>(acc, g_h2, HDIM, W_hh2, HDIM, HDIM, 1, nb, As, Bs, tid);
            stage_z<4>(zs, acc, tid);
            __syncthreads();
            for (int e = tid; e < 4096; e += 128) {
                int row = e >> 5, c = e & 31;
                int col = (c >> 3) * HDIM + nb + (c & 7);
                g_z2p[(size_t)row * 4 * HDIM + col] =
                    zs[row*33 + c] + b_ih2[col] + b_hh2[col];
            }
        }
        gsync();

        // ---------------- Phase B: layer-2, 256 tiles [64 x 32] ----------------
        {
            int rt = jb >> 7;
            int nb = (jb & 127) * 8;
            int m0 = rt * 64;
            ull acc[2][4] = {};
            gemm_tile<2>(acc, h1w + (size_t)m0 * HDIM, HDIM, W_ih2, HDIM, HDIM,
                         1, nb, As, Bs, tid);
            stage_z<2>(zs, acc, tid);
            __syncthreads();
            for (int e = tid; e < 512; e += 128) {
                int row = e >> 3, jj = e & 7;
                int col = nb + jj;
                int grow = m0 + row;
                size_t zb = (size_t)grow * 4 * HDIM + col;
                float zi = zs[row*33 +      jj] + g_z2p[zb];
                float zf = zs[row*33 +  8 + jj] + g_z2p[zb + HDIM];
                float zg = zs[row*33 + 16 + jj] + g_z2p[zb + 2*HDIM];
                float zo = zs[row*33 + 24 + jj] + g_z2p[zb + 3*HDIM];
                int sidx = grow * HDIM + col;
                float cp = g_c2[sidx];
                float cn = sigm(zf) * cp + sigm(zi) * tanhf(zg);
                g_c2[sidx] = cn;
                float h = sigm(zo) * tanhf(cn);
                g_h2[sidx] = h;
                g_hist[(size_t)t * BSZ * HDIM + sidx] = h;
            }
        }
        gsync();
    }
}

// y = hist @ W_out^T + b_out, [T*B, O]; tiles [128 x 32], grid (4, 1024).
__global__ void __launch_bounds__(128, 2)
outproj(const float* __restrict__ W_out, const float* __restrict__ b_out,
        float* __restrict__ y)
{
    __shared__ float smem[5120];
    float* As = smem;
    float* Bs = smem + 4096;
    float* zs = smem;
    int tid = threadIdx.x;
    int m0 = blockIdx.y * 128;
    int nb = blockIdx.x * 32;
    ull acc[4][4] = {};
    gemm_tile<4>(acc, g_hist + (size_t)m0 * HDIM, HDIM, W_out, HDIM, HDIM,
                 0, nb, As, Bs, tid);
    stage_z<4>(zs, acc, tid);
    __syncthreads();
    for (int e = tid; e < 4096; e += 128) {
        int row = e >> 5, c = e & 31;
        y[(size_t)(m0 + row) * ODIM + nb + c] = zs[row*33 + c] + b_out[nb + c];
    }
}

extern "C" void kernel_launch(void* const* d_in, const int* in_sizes, int n_in,
                              void* d_out, int out_size) {
    const float* x     = (const float*)d_in[0];
    const float* W_ih1 = (const float*)d_in[1];
    const float* W_hh1 = (const float*)d_in[2];
    const float* b_ih1 = (const float*)d_in[3];
    const float* b_hh1 = (const float*)d_in[4];
    const float* W_ih2 = (const float*)d_in[5];
    const float* W_hh2 = (const float*)d_in[6];
    const float* b_ih2 = (const float*)d_in[7];
    const float* b_hh2 = (const float*)d_in[8];
    const float* W_out = (const float*)d_in[9];
    const float* b_out = (const float*)d_in[10];

    void *p_h1, *p_c1, *p_h2, *p_c2, *p_bar;
    cudaGetSymbolAddress(&p_h1, g_h1);
    cudaGetSymbolAddress(&p_c1, g_c1);
    cudaGetSymbolAddress(&p_h2, g_h2);
    cudaGetSymbolAddress(&p_c2, g_c2);
    cudaGetSymbolAddress(&p_bar, g_bar);

    size_t sb = (size_t)BSZ * HDIM * sizeof(float);
    cudaMemsetAsync(p_h1, 0, 2 * sb, 0);
    cudaMemsetAsync(p_c1, 0, sb, 0);
    cudaMemsetAsync(p_h2, 0, sb, 0);
    cudaMemsetAsync(p_c2, 0, sb, 0);
    cudaMemsetAsync(p_bar, 0, 2 * sizeof(unsigned), 0);

    lstm_persistent<<<NBLK, 128>>>(x, W_ih1, W_hh1, b_ih1, b_hh1,
                                   W_ih2, W_hh2, b_ih2, b_hh2);
    outproj<<<dim3(4, 1024), 128>>>(W_out, b_out, (float*)d_out);
}

// round 5
// speedup vs baseline: 2.1338x; 2.1258x over previous
#include <cuda_runtime.h>
#include <cuda.h>
#include <cuda_bf16.h>
#include <cstdint>
#include <math.h>

#define TSTEPS 1024
#define BSZ    128
#define DDIM   512
#define HDIM   1024
#define ODIM   128
#define NBLK   128
#define STAGE_BYTES 49152
#define D_BYTES 33792              // 128 rows x 66 floats
#define SMEM_DYN (3 * STAGE_BYTES + D_BYTES + 1024 + 64)

// ---------------- device scratch ----------------
__device__ __nv_bfloat16 g_h1h[2 * BSZ * HDIM], g_h1l[2 * BSZ * HDIM];
__device__ __nv_bfloat16 g_h2h[BSZ * HDIM],     g_h2l[BSZ * HDIM];
__device__ float g_c1[BSZ * HDIM], g_c2[BSZ * HDIM];
__device__ float g_z2p[BSZ * 4 * HDIM];
__device__ float g_hist[(size_t)TSTEPS * BSZ * HDIM];
__device__ __nv_bfloat16 g_xh[(size_t)TSTEPS * BSZ * DDIM];
__device__ __nv_bfloat16 g_xl[(size_t)TSTEPS * BSZ * DDIM];
__device__ __nv_bfloat16 g_w1hh_h[4096 * HDIM], g_w1hh_l[4096 * HDIM];
__device__ __nv_bfloat16 g_w1ih_h[4096 * DDIM], g_w1ih_l[4096 * DDIM];
__device__ __nv_bfloat16 g_w2hh_h[4096 * HDIM], g_w2hh_l[4096 * HDIM];
__device__ __nv_bfloat16 g_w2ih_h[4096 * HDIM], g_w2ih_l[4096 * HDIM];
__device__ float g_bs1[4096], g_bs2[4096];
__device__ unsigned g_bar[2];

typedef unsigned long long ull;

struct Maps {
    CUtensorMap h1h, h1l, h1h64, h1l64, h2h, h2l, xh, xl;
    CUtensorMap w1hh_h, w1hh_l, w1ih_h, w1ih_l;
    CUtensorMap w2hh_h, w2hh_l, w2ih_h, w2ih_l;
};

// ---------------- PTX helpers ----------------
__device__ __forceinline__ uint32_t smem_u32(const void* p) {
    uint32_t a;
    asm("{ .reg .u64 t; cvta.to.shared.u64 t, %1; cvt.u32.u64 %0, t; }" : "=r"(a) : "l"(p));
    return a;
}
#define MBAR_INIT(a, c) asm volatile("mbarrier.init.shared.b64 [%0], %1;" :: "r"(a), "r"(c) : "memory")
#define MBAR_EXPECT(a, n) asm volatile("mbarrier.arrive.expect_tx.shared.b64 _, [%0], %1;" :: "r"(a), "r"(n) : "memory")
#define MBAR_WAIT(a, ph) do { \
    uint32_t _m = (a), _p = (ph), _d; \
    asm volatile("{\n\t.reg .pred p;\n\t" \
        "mbarrier.try_wait.parity.acquire.cta.shared::cta.b64 p, [%1], %2;\n\t" \
        "selp.b32 %0, 1, 0, p;\n\t}" : "=r"(_d) : "r"(_m), "r"(_p) : "memory"); \
    if (!_d) { asm volatile("{\n\t.reg .pred P1;\n\tWL_%=:\n\t" \
        "mbarrier.try_wait.parity.acquire.cta.shared::cta.b64 P1, [%0], %1, 0x989680;\n\t" \
        "@P1 bra.uni WD_%=;\n\tbra.uni WL_%=;\n\tWD_%=:\n\t}" \
        :: "r"(_m), "r"(_p) : "memory"); } \
} while (0)
#define TMA2D(sm, mp, cx, cy, mb) \
    asm volatile("cp.async.bulk.tensor.2d.shared::cta.global.tile.mbarrier::complete_tx::bytes " \
        "[%0], [%1, {%2, %3}], [%4];" \
        :: "r"(sm), "l"(mp), "r"(cx), "r"(cy), "r"(mb) : "memory")

__device__ __forceinline__ void ldsm4(uint32_t (&r)[4], uint32_t addr) {
    asm volatile("ldmatrix.sync.aligned.m8n8.x4.shared.b16 {%0,%1,%2,%3}, [%4];"
        : "=r"(r[0]), "=r"(r[1]), "=r"(r[2]), "=r"(r[3]) : "r"(addr));
}
__device__ __forceinline__ void mma16816(float (&d)[4], const uint32_t (&a)[4],
                                         uint32_t b0, uint32_t b1) {
    asm volatile("mma.sync.aligned.m16n8k16.row.col.f32.bf16.bf16.f32 "
        "{%0,%1,%2,%3}, {%4,%5,%6,%7}, {%8,%9}, {%0,%1,%2,%3};"
        : "+f"(d[0]), "+f"(d[1]), "+f"(d[2]), "+f"(d[3])
        : "r"(a[0]), "r"(a[1]), "r"(a[2]), "r"(a[3]), "r"(b0), "r"(b1));
}
__device__ __forceinline__ float sigm(float x) { return 1.0f / (1.0f + expf(-x)); }
__device__ __forceinline__ void split_bf(float v, __nv_bfloat16* hp, __nv_bfloat16* lp) {
    __nv_bfloat16 h = __float2bfloat16(v);
    *hp = h;
    *lp = __float2bfloat16(v - __bfloat162float(h));
}

__device__ __forceinline__ void gsync() {
    __syncthreads();
    if (threadIdx.x == 0) {
        volatile unsigned* vgen = (volatile unsigned*)&g_bar[1];
        unsigned gen = *vgen;
        __threadfence();
        if (atomicAdd(&g_bar[0], 1u) == NBLK - 1) {
            g_bar[0] = 0;
            __threadfence();
            *vgen = gen + 1;
        } else {
            while (*vgen == gen) { }
        }
        __threadfence();
    }
    __syncthreads();
}

struct Src {
    const CUtensorMap *ah, *al, *bh, *bl;
    int ay, by, nch;
};

// D tile [MTILES*64 x 64] = sum over sources of A@B^T using bf16x3 mma.sync.
// Stage layout per ring slot: Ahi | Alo(+16K) | Bhi(+32K) | Blo(+40K), SW128.
template<int MTILES>
__device__ void mma_tile(uint32_t sbase, float* dptr, uint32_t tail,
                         Src s0, Src s1, uint32_t tx, uint32_t* mu) {
    int tid = threadIdx.x, wid = tid >> 5, lane = tid & 31;
    int m0 = (wid >> 1) * (MTILES * 16);
    int nh = (wid & 1) * 32;
    int total = s0.nch + s1.nch;
    int lrow = lane & 15;
    int lkb  = (lane >> 4) << 4;

    float acc[MTILES][4][4];
    #pragma unroll
    for (int mt = 0; mt < MTILES; mt++)
        #pragma unroll
        for (int nt = 0; nt < 4; nt++)
            #pragma unroll
            for (int q = 0; q < 4; q++) acc[mt][nt][q] = 0.f;

    auto stage = [&](int c) {
        int st = c % 3;
        uint32_t ful = tail + st * 16;
        MBAR_EXPECT(ful, tx);
        uint32_t b = sbase + st * STAGE_BYTES;
        const Src& S = (c < s0.nch) ? s0 : s1;
        int cx = (c < s0.nch ? c : c - s0.nch) * 64;
        TMA2D(b,         S.ah, cx, S.ay, ful);
        TMA2D(b + 16384, S.al, cx, S.ay, ful);
        TMA2D(b + 32768, S.bh, cx, S.by, ful);
        TMA2D(b + 40960, S.bl, cx, S.by, ful);
    };

    if (tid == 0) { stage(0); stage(1); stage(2); }

    for (int c = 0; c < total; c++) {
        int st = c % 3;
        MBAR_WAIT(tail + st * 16, mu[st] & 1);
        mu[st]++;
        uint32_t base = sbase + st * STAGE_BYTES;
        #pragma unroll
        for (int k16 = 0; k16 < 4; k16++) {
            int kb = k16 * 32 + lkb;
            uint32_t ah[MTILES][4], al[MTILES][4], bh[2][4], bl[2][4];
            #pragma unroll
            for (int mt = 0; mt < MTILES; mt++) {
                int r = m0 + mt * 16 + lrow;
                uint32_t off = r * 128 + (kb ^ ((r & 7) << 4));
                ldsm4(ah[mt], base + off);
                ldsm4(al[mt], base + 16384 + off);
            }
            #pragma unroll
            for (int g = 0; g < 2; g++) {
                int r = nh + g * 16 + lrow;
                uint32_t off = r * 128 + (kb ^ ((r & 7) << 4));
                ldsm4(bh[g], base + 32768 + off);
                ldsm4(bl[g], base + 40960 + off);
            }
            // product 0: Ahi*Bhi, 1: Ahi*Blo, 2: Alo*Bhi — interleaved for ILP
            #pragma unroll
            for (int mt = 0; mt < MTILES; mt++)
                #pragma unroll
                for (int nt = 0; nt < 4; nt++)
                    mma16816(acc[mt][nt], ah[mt], bh[nt>>1][nt&1], bh[nt>>1][2+(nt&1)]);
            #pragma unroll
            for (int mt = 0; mt < MTILES; mt++)
                #pragma unroll
                for (int nt = 0; nt < 4; nt++)
                    mma16816(acc[mt][nt], ah[mt], bl[nt>>1][nt&1], bl[nt>>1][2+(nt&1)]);
            #pragma unroll
            for (int mt = 0; mt < MTILES; mt++)
                #pragma unroll
                for (int nt = 0; nt < 4; nt++)
                    mma16816(acc[mt][nt], al[mt], bh[nt>>1][nt&1], bh[nt>>1][2+(nt&1)]);
        }
        __syncthreads();
        if (tid == 0 && c + 3 < total) stage(c + 3);
    }
    // write D to smem (row stride 66)
    int dr = m0 + (lane >> 2);
    int dc = nh + (lane & 3) * 2;
    #pragma unroll
    for (int mt = 0; mt < MTILES; mt++)
        #pragma unroll
        for (int nt = 0; nt < 4; nt++) {
            *(float2*)(dptr + (dr + mt*16    ) * 66 + dc + nt*8) = make_float2(acc[mt][nt][0], acc[mt][nt][1]);
            *(float2*)(dptr + (dr + mt*16 + 8) * 66 + dc + nt*8) = make_float2(acc[mt][nt][2], acc[mt][nt][3]);
        }
    __syncthreads();
}

__global__ void __launch_bounds__(256, 1) lstm_mma(const __grid_constant__ Maps maps) {
    extern __shared__ char dsm[];
    uint32_t raw = smem_u32(dsm);
    uint32_t sbase = (raw + 1023) & ~1023u;
    float* dptr = (float*)(dsm + (sbase - raw) + 3 * STAGE_BYTES);
    uint32_t tail = sbase + 3 * STAGE_BYTES + D_BYTES;
    int tid = threadIdx.x, jb = blockIdx.x;

    if (tid == 0)
        for (int s = 0; s < 3; s++) MBAR_INIT(tail + s * 16, 1);
    __syncthreads();

    uint32_t mu[3] = {0, 0, 0};

    for (int t = 0; t < TSTEPS; t++) {
        int rb = (t & 1) * 128, wb = ((t + 1) & 1) * 128;
        __nv_bfloat16* h1wh = g_h1h + (size_t)wb * HDIM;
        __nv_bfloat16* h1wl = g_h1l + (size_t)wb * HDIM;

        // ---- Phase A ----
        if (jb < 64) {
            Src sH = {&maps.h1h, &maps.h1l, &maps.w1hh_h, &maps.w1hh_l, rb, jb * 64, 16};
            Src sX = {&maps.xh,  &maps.xl,  &maps.w1ih_h, &maps.w1ih_l, t * 128, jb * 64, 8};
            mma_tile<2>(sbase, dptr, tail, sH, sX, 49152u, mu);
            const float* bs = g_bs1 + jb * 64;
            for (int e = tid; e < 2048; e += 256) {
                int row = e >> 4, u = e & 15;
                const float* drw = dptr + row * 66 + u * 4;
                float zi = drw[0] + bs[u*4+0];
                float zf = drw[1] + bs[u*4+1];
                float zg = drw[2] + bs[u*4+2];
                float zo = drw[3] + bs[u*4+3];
                int idx = row * HDIM + jb * 16 + u;
                float cn = sigm(zf) * g_c1[idx] + sigm(zi) * tanhf(zg);
                g_c1[idx] = cn;
                split_bf(sigm(zo) * tanhf(cn), &h1wh[idx], &h1wl[idx]);
            }
        } else {
            int j = jb - 64;
            Src sH = {&maps.h2h, &maps.h2l, &maps.w2hh_h, &maps.w2hh_l, 0, j * 64, 16};
            Src sZ = {0, 0, 0, 0, 0, 0, 0};
            mma_tile<2>(sbase, dptr, tail, sH, sZ, 49152u, mu);
            const float* bs = g_bs2 + j * 64;
            for (int e = tid; e < 8192; e += 256) {
                int row = e >> 6, c = e & 63;
                g_z2p[row * 4096 + j * 64 + c] = dptr[row * 66 + c] + bs[c];
            }
        }
        gsync();

        // ---- Phase B: layer-2 over all 128 CTAs (M=64 halves) ----
        {
            int j = jb & 63, mh = jb >> 6;
            Src sH = {&maps.h1h64, &maps.h1l64, &maps.w2ih_h, &maps.w2ih_l,
                      wb + mh * 64, j * 64, 16};
            Src sZ = {0, 0, 0, 0, 0, 0, 0};
            mma_tile<1>(sbase, dptr, tail, sH, sZ, 32768u, mu);
            for (int e = tid; e < 1024; e += 256) {
                int row = e >> 4, u = e & 15;
                int grow = mh * 64 + row;
                const float* drw = dptr + row * 66 + u * 4;
                const float4 z = __ldcg((const float4*)(g_z2p + grow * 4096 + j * 64 + u * 4));
                float zi = drw[0] + z.x;
                float zf = drw[1] + z.y;
                float zg = drw[2] + z.z;
                float zo = drw[3] + z.w;
                int idx = grow * HDIM + j * 16 + u;
                float cn = sigm(zf) * g_c2[idx] + sigm(zi) * tanhf(zg);
                g_c2[idx] = cn;
                float h = sigm(zo) * tanhf(cn);
                g_hist[(size_t)t * BSZ * HDIM + idx] = h;
                split_bf(h, &g_h2h[idx], &g_h2l[idx]);
            }
        }
        gsync();
    }
}

// ---------------- prepass ----------------
__global__ void conv_w(const float* __restrict__ W, __nv_bfloat16* hi, __nv_bfloat16* lo, int K) {
    int n = 4096 * K;
    for (int i = blockIdx.x * blockDim.x + threadIdx.x; i < n; i += gridDim.x * blockDim.x) {
        int r = i / K, k = i - r * K;
        int sr = (r & 3) * HDIM + (r >> 2);
        float w = W[(size_t)sr * K + k];
        __nv_bfloat16 h = __float2bfloat16(w);
        hi[i] = h;
        lo[i] = __float2bfloat16(w - __bfloat162float(h));
    }
}
__global__ void conv_x(const float* __restrict__ x, __nv_bfloat16* hi, __nv_bfloat16* lo, int n) {
    for (int i = blockIdx.x * blockDim.x + threadIdx.x; i < n; i += gridDim.x * blockDim.x) {
        float w = x[i];
        __nv_bfloat16 h = __float2bfloat16(w);
        hi[i] = h;
        lo[i] = __float2bfloat16(w - __bfloat162float(h));
    }
}
__global__ void conv_b(const float* bi, const float* bh, float* bs) {
    int i = blockIdx.x * blockDim.x + threadIdx.x;
    if (i < 4096) {
        int sr = (i & 3) * HDIM + (i >> 2);
        bs[i] = bi[sr] + bh[sr];
    }
}
__global__ void zero_state() {
    int i = blockIdx.x * blockDim.x + threadIdx.x;
    if (i < BSZ * HDIM) {
        g_c1[i] = 0.f; g_c2[i] = 0.f;
        g_h1h[i] = __float2bfloat16(0.f); g_h1l[i] = __float2bfloat16(0.f);
        g_h1h[BSZ*HDIM + i] = __float2bfloat16(0.f); g_h1l[BSZ*HDIM + i] = __float2bfloat16(0.f);
        g_h2h[i] = __float2bfloat16(0.f); g_h2l[i] = __float2bfloat16(0.f);
    }
    if (i < 2) g_bar[i] = 0u;
}

// ---------------- output projection (FFMA2) ----------------
#define FMA2(dst, a, b) asm("fma.rn.f32x2 %0, %1, %2, %0;" : "+l"(dst) : "l"(a), "l"(b))
__device__ __forceinline__ ull dup2(float b) {
    ull r; asm("mov.b64 %0, {%1, %1};" : "=l"(r) : "f"(b)); return r;
}
__device__ __forceinline__ float2 unpk(ull v) {
    float2 r; asm("mov.b64 {%0, %1}, %2;" : "=f"(r.x), "=f"(r.y) : "l"(v)); return r;
}

__global__ void __launch_bounds__(128, 2)
outproj(const float* __restrict__ W_out, const float* __restrict__ b_out, float* __restrict__ y)
{
    __shared__ float smem[5120];
    float* As = smem; float* Bs = smem + 4096; float* zs = smem;
    int tid = threadIdx.x;
    int m0 = blockIdx.y * 128, nb = blockIdx.x * 32;
    int r0 = (tid >> 3) * 8, c0 = (tid & 7) * 4;
    const float* A = g_hist + (size_t)m0 * HDIM;
    ull acc[4][4] = {};
    for (int k0 = 0; k0 < HDIM; k0 += 32) {
        #pragma unroll
        for (int i = 0; i < 8; i++) {
            int f4 = tid + i * 128, rw = f4 >> 3, kc = (f4 & 7) << 2;
            float4 v = *(const float4*)(A + (size_t)rw * HDIM + k0 + kc);
            int sw = kc & 28;
            As[(kc+0)*128 + (rw^sw)] = v.x; As[(kc+1)*128 + (rw^sw)] = v.y;
            As[(kc+2)*128 + (rw^sw)] = v.z; As[(kc+3)*128 + (rw^sw)] = v.w;
        }
        #pragma unroll
        for (int i = 0; i < 2; i++) {
            int f4 = tid + i * 128, cl = f4 >> 3, kc = (f4 & 7) << 2;
            float4 v = *(const float4*)(W_out + (size_t)(nb + cl) * HDIM + k0 + kc);
            int sw = kc & 28;
            Bs[(kc+0)*32 + (cl^sw)] = v.x; Bs[(kc+1)*32 + (cl^sw)] = v.y;
            Bs[(kc+2)*32 + (cl^sw)] = v.z; Bs[(kc+3)*32 + (cl^sw)] = v.w;
        }
        __syncthreads();
        #pragma unroll
        for (int kk = 0; kk < 32; kk++) {
            int sw = kk & 28;
            float4 bv = *(const float4*)&Bs[kk * 32 + (c0 ^ sw)];
            ull b0 = dup2(bv.x), b1 = dup2(bv.y), b2 = dup2(bv.z), b3 = dup2(bv.w);
            #pragma unroll
            for (int rp = 0; rp < 2; rp++) {
                ulonglong2 av = *(const ulonglong2*)&As[kk * 128 + ((r0 + rp * 4) ^ sw)];
                FMA2(acc[rp*2+0][0], av.x, b0); FMA2(acc[rp*2+0][1], av.x, b1);
                FMA2(acc[rp*2+0][2], av.x, b2); FMA2(acc[rp*2+0][3], av.x, b3);
                FMA2(acc[rp*2+1][0], av.y, b0); FMA2(acc[rp*2+1][1], av.y, b1);
                FMA2(acc[rp*2+1][2], av.y, b2); FMA2(acc[rp*2+1][3], av.y, b3);
            }
        }
        __syncthreads();
    }
    #pragma unroll
    for (int rp = 0; rp < 4; rp++)
        #pragma unroll
        for (int c = 0; c < 4; c++) {
            float2 v = unpk(acc[rp][c]);
            zs[(r0 + 2*rp + 0) * 33 + c0 + c] = v.x;
            zs[(r0 + 2*rp + 1) * 33 + c0 + c] = v.y;
        }
    __syncthreads();
    for (int e = tid; e < 4096; e += 128) {
        int rw = e >> 5, c = e & 31;
        y[(size_t)(m0 + rw) * ODIM + nb + c] = zs[rw*33 + c] + b_out[nb + c];
    }
}

// ---------------- host ----------------
typedef CUresult (*PFN_enc)(CUtensorMap*, CUtensorMapDataType, cuuint32_t, void*,
    const cuuint64_t*, const cuuint64_t*, const cuuint32_t*, const cuuint32_t*,
    CUtensorMapInterleave, CUtensorMapSwizzle, CUtensorMapL2promotion, CUtensorMapFloatOOBfill);

static void enc(PFN_enc fn, CUtensorMap* m, void* ptr, int K, uint64_t rows, uint32_t boxRows) {
    cuuint64_t dims[2] = {(cuuint64_t)K, (cuuint64_t)rows};
    cuuint64_t str[1]  = {(cuuint64_t)K * 2};
    cuuint32_t box[2]  = {64u, boxRows};
    cuuint32_t es[2]   = {1u, 1u};
    fn(m, CU_TENSOR_MAP_DATA_TYPE_BFLOAT16, 2, ptr, dims, str, box, es,
       CU_TENSOR_MAP_INTERLEAVE_NONE, CU_TENSOR_MAP_SWIZZLE_128B,
       CU_TENSOR_MAP_L2_PROMOTION_L2_128B, CU_TENSOR_MAP_FLOAT_OOB_FILL_NONE);
}

extern "C" void kernel_launch(void* const* d_in, const int* in_sizes, int n_in,
                              void* d_out, int out_size) {
    const float* x     = (const float*)d_in[0];
    const float* W_ih1 = (const float*)d_in[1];
    const float* W_hh1 = (const float*)d_in[2];
    const float* b_ih1 = (const float*)d_in[3];
    const float* b_hh1 = (const float*)d_in[4];
    const float* W_ih2 = (const float*)d_in[5];
    const float* W_hh2 = (const float*)d_in[6];
    const float* b_ih2 = (const float*)d_in[7];
    const float* b_hh2 = (const float*)d_in[8];
    const float* W_out = (const float*)d_in[9];
    const float* b_out = (const float*)d_in[10];

    cudaFuncSetAttribute(lstm_mma, cudaFuncAttributeMaxDynamicSharedMemorySize, SMEM_DYN);

    void *ph1h, *ph1l, *ph2h, *ph2l, *pxh, *pxl;
    void *pa, *pb, *pc, *pd, *pe, *pf, *pg, *ph, *pbs1, *pbs2;
    cudaGetSymbolAddress(&ph1h, g_h1h); cudaGetSymbolAddress(&ph1l, g_h1l);
    cudaGetSymbolAddress(&ph2h, g_h2h); cudaGetSymbolAddress(&ph2l, g_h2l);
    cudaGetSymbolAddress(&pxh, g_xh);   cudaGetSymbolAddress(&pxl, g_xl);
    cudaGetSymbolAddress(&pa, g_w1hh_h); cudaGetSymbolAddress(&pb, g_w1hh_l);
    cudaGetSymbolAddress(&pc, g_w1ih_h); cudaGetSymbolAddress(&pd, g_w1ih_l);
    cudaGetSymbolAddress(&pe, g_w2hh_h); cudaGetSymbolAddress(&pf, g_w2hh_l);
    cudaGetSymbolAddress(&pg, g_w2ih_h); cudaGetSymbolAddress(&ph, g_w2ih_l);
    cudaGetSymbolAddress(&pbs1, g_bs1);  cudaGetSymbolAddress(&pbs2, g_bs2);

    PFN_enc fn = 0;
    cudaDriverEntryPointQueryResult qres;
    cudaGetDriverEntryPoint("cuTensorMapEncodeTiled", (void**)&fn, cudaEnableDefault, &qres);

    Maps mp;
    enc(fn, &mp.h1h, ph1h, HDIM, 256, 128);   enc(fn, &mp.h1l, ph1l, HDIM, 256, 128);
    enc(fn, &mp.h1h64, ph1h, HDIM, 256, 64);  enc(fn, &mp.h1l64, ph1l, HDIM, 256, 64);
    enc(fn, &mp.h2h, ph2h, HDIM, 128, 128);   enc(fn, &mp.h2l, ph2l, HDIM, 128, 128);
    enc(fn, &mp.xh,  pxh, DDIM, (uint64_t)TSTEPS * BSZ, 128);
    enc(fn, &mp.xl,  pxl, DDIM, (uint64_t)TSTEPS * BSZ, 128);
    enc(fn, &mp.w1hh_h, pa, HDIM, 4096, 64);  enc(fn, &mp.w1hh_l, pb, HDIM, 4096, 64);
    enc(fn, &mp.w1ih_h, pc, DDIM, 4096, 64);  enc(fn, &mp.w1ih_l, pd, DDIM, 4096, 64);
    enc(fn, &mp.w2hh_h, pe, HDIM, 4096, 64);  enc(fn, &mp.w2hh_l, pf, HDIM, 4096, 64);
    enc(fn, &mp.w2ih_h, pg, HDIM, 4096, 64);  enc(fn, &mp.w2ih_l, ph, HDIM, 4096, 64);

    conv_w<<<2048, 256>>>(W_hh1, (__nv_bfloat16*)pa, (__nv_bfloat16*)pb, HDIM);
    conv_w<<<1024, 256>>>(W_ih1, (__nv_bfloat16*)pc, (__nv_bfloat16*)pd, DDIM);
    conv_w<<<2048, 256>>>(W_hh2, (__nv_bfloat16*)pe, (__nv_bfloat16*)pf, HDIM);
    conv_w<<<2048, 256>>>(W_ih2, (__nv_bfloat16*)pg, (__nv_bfloat16*)ph, HDIM);
    conv_b<<<16, 256>>>(b_ih1, b_hh1, (float*)pbs1);
    conv_b<<<16, 256>>>(b_ih2, b_hh2, (float*)pbs2);
    conv_x<<<4096, 256>>>(x, (__nv_bfloat16*)pxh, (__nv_bfloat16*)pxl, TSTEPS * BSZ * DDIM);
    zero_state<<<512, 256>>>();

    lstm_mma<<<NBLK, 256, SMEM_DYN>>>(mp);
    outproj<<<dim3(4, 1024), 128>>>(W_out, b_out, (float*)d_out);
}